// round 2
// baseline (speedup 1.0000x reference)
#include <cuda_runtime.h>
#include <cuda_bf16.h>

#define BATCH 256
#define TM1   63
#define NI    128
#define NH    128
#define GB    2
#define NCTA  (BATCH/GB)
#define NTHR  256

// Scratch (device globals: allocation-free rule)
__device__ float g_P[BATCH*TM1*NI];        // 8.25 MB: P[b][t][o] = aW1_x . X[b,t] + ab1
__device__ float g_WhhT[NH*4*NH];          // [128][512]  WhhT[k][j] = Whh[j][k]
__device__ float g_aW1hcT[2*NH*NI];        // [256][128]  aW1hcT[k][i] = aW1[i][k], k<256

__device__ __forceinline__ float warp_sum(float v){
    v += __shfl_xor_sync(0xffffffffu, v, 16);
    v += __shfl_xor_sync(0xffffffffu, v, 8);
    v += __shfl_xor_sync(0xffffffffu, v, 4);
    v += __shfl_xor_sync(0xffffffffu, v, 2);
    v += __shfl_xor_sync(0xffffffffu, v, 1);
    return v;
}

// accurate-enough tanh/sigmoid from MUFU exp (~2^-21 rel err)
__device__ __forceinline__ float ftanh(float x){
    float ax = fabsf(x);
    float e  = __expf(-2.0f*ax);
    float t  = __fdividef(1.0f - e, 1.0f + e);
    return (x < 0.0f) ? -t : t;
}
__device__ __forceinline__ float fsig(float x){
    return __fdividef(1.0f, 1.0f + __expf(-x));
}

// ---------------- prep: weight transposes ----------------
__global__ void prep_kernel(const float* __restrict__ aW1, const float* __restrict__ Whh){
    int tid = blockIdx.x*blockDim.x + threadIdx.x;
    int stride = gridDim.x*blockDim.x;
    for (int idx = tid; idx < 128*512; idx += stride){
        int k = idx >> 9, j = idx & 511;
        g_WhhT[idx] = Whh[j*128 + k];
    }
    for (int idx = tid; idx < 256*128; idx += stride){
        int k = idx >> 7, i = idx & 127;
        g_aW1hcT[idx] = aW1[i*384 + k];
    }
}

// ---------------- P precompute: P[b,t,o] = ab1[o] + sum_k X[b,t,k]*aW1[o,256+k] ----------------
__global__ void p_kernel(const float* __restrict__ X, const float* __restrict__ aW1,
                         const float* __restrict__ ab1){
    extern __shared__ char sraw[];
    float* Xs   = (float*)sraw;        // 8192 floats (padded; t=63 row zeroed)
    float* WT   = Xs + 8192;           // 128*129 padded transpose of aW1 x-part
    float* ab1s = WT + 128*129;        // 128
    int b = blockIdx.x, tid = threadIdx.x;

    for (int idx = tid; idx < 8192; idx += NTHR)
        Xs[idx] = (idx < TM1*NI) ? X[b*TM1*NI + idx] : 0.0f;
    for (int idx = tid; idx < 128*128; idx += NTHR){
        int o = idx >> 7, k = idx & 127;
        WT[k*129 + o] = aW1[o*384 + 256 + k];
    }
    if (tid < 128) ab1s[tid] = ab1[tid];
    __syncthreads();

    int o = tid & 127, half = tid >> 7;
    for (int tb = 0; tb < 8; tb++){
        int tbase = half*32 + tb*4;
        float bv = ab1s[o];
        float a0 = bv, a1 = bv, a2 = bv, a3 = bv;
        #pragma unroll 4
        for (int k = 0; k < 128; k++){
            float w = WT[k*129 + o];
            a0 = fmaf(Xs[(tbase+0)*128+k], w, a0);
            a1 = fmaf(Xs[(tbase+1)*128+k], w, a1);
            a2 = fmaf(Xs[(tbase+2)*128+k], w, a2);
            a3 = fmaf(Xs[(tbase+3)*128+k], w, a3);
        }
        if (tbase+0 < TM1) g_P[b*TM1*NI + (tbase+0)*128 + o] = a0;
        if (tbase+1 < TM1) g_P[b*TM1*NI + (tbase+1)*128 + o] = a1;
        if (tbase+2 < TM1) g_P[b*TM1*NI + (tbase+2)*128 + o] = a2;
        if (tbase+3 < TM1) g_P[b*TM1*NI + (tbase+3)*128 + o] = a3;
    }
}

// ---------------- main persistent recurrence ----------------
struct __align__(16) SmemMain {
    float Xs[GB][TM1][NI];    // 64512 B
    float Ps[GB][TM1][NI];    // 64512 B
    float qs[GB][NI];
    float ctx[GB][NI];
    float aw2[NI];
    float wfc[132];           // [0..127] = Wfc[1..128], [128] = Wfc[0]
    float wo[2*NI];
    float hc[2*NH][GB];       // [k][g], k<128 -> h, k>=128 -> c
    float qpart[4][GB][NI];
    float gatesH[GB][4*NH];
    float sc[GB][64];
    float be[GB][64];
    float wih[4*NH];
    float bsum[4*NH];
    float ssum[GB];
    float yup[GB];
};

__global__ void __launch_bounds__(NTHR, 1) main_kernel(
    const float* __restrict__ X, const float* __restrict__ Y,
    const float* __restrict__ aW2,
    const float* __restrict__ Wih, const float* __restrict__ bih, const float* __restrict__ bhh,
    const float* __restrict__ Wfc, const float* __restrict__ bfc,
    const float* __restrict__ Wo,  const float* __restrict__ bo,
    float* __restrict__ out)
{
    extern __shared__ char smraw[];
    SmemMain* sm = (SmemMain*)smraw;
    int tid = threadIdx.x;
    int b0  = blockIdx.x * GB;
    int w = tid >> 5, lane = tid & 31;

    // stage X, P, small weights
    for (int idx = tid; idx < GB*TM1*NI; idx += NTHR){
        ((float*)sm->Xs)[idx] = X[b0*TM1*NI + idx];
        ((float*)sm->Ps)[idx] = g_P[b0*TM1*NI + idx];
    }
    for (int idx = tid; idx < 4*NH; idx += NTHR){
        sm->wih[idx]  = Wih[idx];
        sm->bsum[idx] = bih[idx] + bhh[idx];
    }
    if (tid < NI)  sm->aw2[tid] = aW2[tid];
    if (tid < 128) sm->wfc[tid] = Wfc[tid+1];
    if (tid == 128) sm->wfc[128] = Wfc[0];
    if (tid < 2*NI) sm->wo[tid] = Wo[tid];
    for (int idx = tid; idx < 2*NH*GB; idx += NTHR) ((float*)sm->hc)[idx] = 0.0f;
    __syncthreads();

    for (int t = 0; t < TM1; t++){
        // ---- phase 1a: gatesH[g][j] = Whh[j,:] . h_g  (thread owns j=2*tid, 2*tid+1)
        {
            const float2* W2  = (const float2*)g_WhhT;     // row k: 256 float2
            const float2* hcp = (const float2*)sm->hc;     // (h_g0, h_g1) per k
            float a00=0.f, a01=0.f, a10=0.f, a11=0.f;
            #pragma unroll 8
            for (int k = 0; k < NH; k++){
                float2 wv = W2[k*256 + tid];
                float2 h2 = hcp[k];
                a00 = fmaf(wv.x, h2.x, a00); a01 = fmaf(wv.y, h2.x, a01);
                a10 = fmaf(wv.x, h2.y, a10); a11 = fmaf(wv.y, h2.y, a11);
            }
            sm->gatesH[0][2*tid]   = a00; sm->gatesH[0][2*tid+1] = a01;
            sm->gatesH[1][2*tid]   = a10; sm->gatesH[1][2*tid+1] = a11;
        }
        // ---- phase 1b: q partial dots (quarter of k-range per thread group)
        {
            int qt = tid >> 6, il = tid & 63;
            const float2* W2  = (const float2*)g_aW1hcT;   // row k: 64 float2
            const float2* hcp = (const float2*)sm->hc;
            float a00=0.f, a01=0.f, a10=0.f, a11=0.f;
            #pragma unroll 8
            for (int kk = 0; kk < 64; kk++){
                int k = qt*64 + kk;
                float2 wv = W2[k*64 + il];
                float2 h2 = hcp[k];
                a00 = fmaf(wv.x, h2.x, a00); a01 = fmaf(wv.y, h2.x, a01);
                a10 = fmaf(wv.x, h2.y, a10); a11 = fmaf(wv.y, h2.y, a11);
            }
            sm->qpart[qt][0][2*il] = a00; sm->qpart[qt][0][2*il+1] = a01;
            sm->qpart[qt][1][2*il] = a10; sm->qpart[qt][1][2*il+1] = a11;
        }
        __syncthreads();
        // combine q quarters
        {
            int g = tid >> 7, i = tid & 127;
            sm->qs[g][i] = sm->qpart[0][g][i] + sm->qpart[1][g][i]
                         + sm->qpart[2][g][i] + sm->qpart[3][g][i];
        }
        __syncthreads();
        // ---- scores: warps 0-3 -> g=0, warps 4-7 -> g=1
        {
            int g = w >> 2, gw = w & 3;
            float4 a2 = ((const float4*)sm->aw2)[lane];
            float4 qv = ((const float4*)sm->qs[g])[lane];
            for (int tt = gw; tt < TM1; tt += 4){
                float4 p = ((const float4*)sm->Ps[g][tt])[lane];
                float sv = a2.x*ftanh(p.x+qv.x) + a2.y*ftanh(p.y+qv.y)
                         + a2.z*ftanh(p.z+qv.z) + a2.w*ftanh(p.w+qv.w);
                sv = warp_sum(sv);
                if (lane == 0) sm->sc[g][tt] = sv;
            }
        }
        __syncthreads();
        // ---- softmax (warps 0 and 4), keep unnormalized exp + sum
        if ((w & 3) == 0){
            int g = w >> 2;
            float s0 = sm->sc[g][lane];
            float s1 = (lane < 31) ? sm->sc[g][32+lane] : -3.0e38f;
            float m = fmaxf(s0, s1);
            #pragma unroll
            for (int off = 16; off > 0; off >>= 1)
                m = fmaxf(m, __shfl_xor_sync(0xffffffffu, m, off));
            float e0 = __expf(s0 - m);
            float e1 = (lane < 31) ? __expf(s1 - m) : 0.0f;
            float ssv = warp_sum(e0 + e1);
            sm->be[g][lane] = e0;
            if (lane < 31) sm->be[g][32+lane] = e1;
            if (lane == 0) sm->ssum[g] = ssv;
        }
        __syncthreads();
        // ---- context
        {
            int g = tid >> 7, i = tid & 127;
            float acc = 0.0f;
            #pragma unroll
            for (int tt = 0; tt < TM1; tt++)
                acc = fmaf(sm->be[g][tt], sm->Xs[g][tt][i], acc);
            sm->ctx[g][i] = acc * __fdividef(1.0f, sm->ssum[g]);
        }
        __syncthreads();
        // ---- y_update (warps 0 and 4)
        if ((w & 3) == 0){
            int g = w >> 2;
            float4 wf = ((const float4*)sm->wfc)[lane];
            float4 cv = ((const float4*)sm->ctx[g])[lane];
            float acc = wf.x*cv.x + wf.y*cv.y + wf.z*cv.z + wf.w*cv.w;
            acc = warp_sum(acc);
            if (lane == 0){
                float yt = Y[(b0+g)*TM1 + t];
                sm->yup[g] = bfc[0] + sm->wfc[128]*yt + acc;
            }
        }
        __syncthreads();
        // ---- LSTM cell
        {
            int g = tid >> 7, jj = tid & 127;
            float yu = sm->yup[g];
            float gi = sm->gatesH[g][jj]        + yu*sm->wih[jj]        + sm->bsum[jj];
            float gf = sm->gatesH[g][NH+jj]     + yu*sm->wih[NH+jj]     + sm->bsum[NH+jj];
            float gg = sm->gatesH[g][2*NH+jj]   + yu*sm->wih[2*NH+jj]   + sm->bsum[2*NH+jj];
            float go = sm->gatesH[g][3*NH+jj]   + yu*sm->wih[3*NH+jj]   + sm->bsum[3*NH+jj];
            float co = sm->hc[NH+jj][g];
            float cn = fsig(gf)*co + fsig(gi)*ftanh(gg);
            float hn = fsig(go)*ftanh(cn);
            sm->hc[jj][g]    = hn;
            sm->hc[NH+jj][g] = cn;
        }
        __syncthreads();
    }

    // ---- output: y[b] = bo + Wo[0:128].h + Wo[128:256].ctx
    if ((w & 3) == 0){
        int g = w >> 2;
        float acc = 0.0f;
        #pragma unroll
        for (int r = 0; r < 4; r++){
            int i = lane*4 + r;
            acc += sm->wo[i]*sm->hc[i][g] + sm->wo[NI+i]*sm->ctx[g][i];
        }
        acc = warp_sum(acc);
        if (lane == 0) out[b0 + g] = acc + bo[0];
    }
}

extern "C" void kernel_launch(void* const* d_in, const int* in_sizes, int n_in,
                              void* d_out, int out_size) {
    const float* X   = (const float*)d_in[0];
    const float* Y   = (const float*)d_in[1];
    const float* aW1 = (const float*)d_in[2];
    const float* ab1 = (const float*)d_in[3];
    const float* aW2 = (const float*)d_in[4];
    // d_in[5] = ab2: constant softmax shift, mathematically irrelevant
    const float* Wih = (const float*)d_in[6];
    const float* Whh = (const float*)d_in[7];
    const float* bih = (const float*)d_in[8];
    const float* bhh = (const float*)d_in[9];
    const float* Wfc = (const float*)d_in[10];
    const float* bfc = (const float*)d_in[11];
    const float* Wo  = (const float*)d_in[12];
    const float* bo  = (const float*)d_in[13];
    float* out = (float*)d_out;

    size_t p_smem = (size_t)(8192 + 128*129 + 128) * sizeof(float);
    size_t m_smem = sizeof(SmemMain);
    cudaFuncSetAttribute(p_kernel,    cudaFuncAttributeMaxDynamicSharedMemorySize, (int)p_smem);
    cudaFuncSetAttribute(main_kernel, cudaFuncAttributeMaxDynamicSharedMemorySize, (int)m_smem);

    prep_kernel<<<64, 256>>>(aW1, Whh);
    p_kernel<<<BATCH, NTHR, p_smem>>>(X, aW1, ab1);
    main_kernel<<<NCTA, NTHR, m_smem>>>(X, Y, aW2, Wih, bih, bhh, Wfc, bfc, Wo, bo, out);
}